// round 13
// baseline (speedup 1.0000x reference)
#include <cuda_runtime.h>
#include <cuda_bf16.h>
#include <math_constants.h>

#define Np 16384
#define Dd 128
#define Hh 128
#define Cc 10
#define Kk 32
#define CAND 64         // pass-1 candidates per row (top-64 superset of true top-32)

#define BM 128          // query rows per block
#define BN 64           // candidate cols per chunk
#define NCHUNK (Np / BN)

// shared memory byte offsets (pass-1 knn kernel)
#define SM_CSQ  64                           // float[2][64]
#define SM_A    1024                         // 2 half-tiles x 16384 B : 128 rows x 128B SW128
#define SM_B    (SM_A + 2 * 16384)           // 2 half-tiles x 8192 B : 64 rows x 128B SW128
#define SM_TOPD (SM_B + 2 * 8192)            // float[128][65]
#define SM_TOPI (SM_TOPD + 128 * 65 * 4)     // int[128][65]
#define SM_D2   (SM_TOPI + 128 * 65 * 4)     // float[128][65]
#define SMEM_TOTAL (SM_D2 + 128 * 65 * 4)    // 150016 B

__device__ __forceinline__ unsigned sw128(unsigned off) { return off ^ ((off >> 3) & 0x70); }

// -------------------- scratch (static device memory) -----------------------
__device__ float d_sq[Np];
__device__ int   d_cand[Np * CAND];
__device__ int   d_idx[Np * Kk];
__device__ float d_u[Np * Hh];
__device__ float d_B[Np * Hh];
__device__ float d_h[Np * Hh];
__device__ float d_v[Np * Cc];
__device__ float d_Dm[Np * Cc];
__device__ __nv_bfloat16 d_Xh[Np * Dd];

// -------------------- ptx helpers ------------------------------------------
__device__ __forceinline__ unsigned smem_u32(const void* p) {
    unsigned a;
    asm("{ .reg .u64 t; cvta.to.shared.u64 t, %1; cvt.u32.u64 %0, t; }" : "=r"(a) : "l"(p));
    return a;
}
__device__ __forceinline__ void ldmx4(unsigned& r0, unsigned& r1, unsigned& r2, unsigned& r3,
                                      unsigned addr) {
    asm volatile("ldmatrix.sync.aligned.m8n8.x4.shared.b16 {%0,%1,%2,%3}, [%4];"
                 : "=r"(r0), "=r"(r1), "=r"(r2), "=r"(r3) : "r"(addr));
}
__device__ __forceinline__ void mma16816(float* d, const unsigned* a, unsigned b0, unsigned b1) {
    asm volatile("mma.sync.aligned.m16n8k16.row.col.f32.bf16.bf16.f32 "
                 "{%0,%1,%2,%3}, {%4,%5,%6,%7}, {%8,%9}, {%0,%1,%2,%3};"
                 : "+f"(d[0]), "+f"(d[1]), "+f"(d[2]), "+f"(d[3])
                 : "r"(a[0]), "r"(a[1]), "r"(a[2]), "r"(a[3]), "r"(b0), "r"(b1));
}
__device__ __forceinline__ void cpasync16(unsigned dst, const void* src) {
    asm volatile("cp.async.cg.shared.global [%0], [%1], 16;" :: "r"(dst), "l"(src) : "memory");
}
#define CP_COMMIT() asm volatile("cp.async.commit_group;" ::: "memory")
#define CP_WAIT0()  asm volatile("cp.async.wait_group 0;" ::: "memory")

// ---------------------------------------------------------------------------
// 0) bf16 copy of X (hh term only needed for pass-1)
// ---------------------------------------------------------------------------
__global__ void convert_kernel(const float* __restrict__ X) {
    int i = blockIdx.x * 256 + threadIdx.x;
    d_Xh[i] = __float2bfloat16(X[i]);
}

// ---------------------------------------------------------------------------
// 1) row squared norms
// ---------------------------------------------------------------------------
__global__ void sq_kernel(const float* __restrict__ X) {
    int row = blockIdx.x * 8 + threadIdx.y;
    const float4* xr = (const float4*)(X + (size_t)row * Dd);
    float4 v = xr[threadIdx.x];
    float s = v.x * v.x + v.y * v.y + v.z * v.z + v.w * v.w;
    #pragma unroll
    for (int o = 16; o > 0; o >>= 1) s += __shfl_xor_sync(0xffffffffu, s, o);
    if (threadIdx.x == 0) d_sq[row] = s;
}

// ---------------------------------------------------------------------------
// 2) PASS 1: bf16 mma.sync distance GEMM (hh only) + approx top-64
//    d2a = sq_j - 2 * dot(h_i, h_j)
// ---------------------------------------------------------------------------
__global__ __launch_bounds__(256, 1) void knn_kernel() {
    extern __shared__ char smem[];
    const unsigned sb = smem_u32(smem);
    const int tid  = threadIdx.x;
    const int lane = tid & 31;
    const int w    = tid >> 5;
    const int row0 = blockIdx.x * BM;

    float* csq  = (float*)(smem + SM_CSQ);
    float* topd = (float*)(smem + SM_TOPD);
    int*   topi = (int*)  (smem + SM_TOPI);
    float* d2s  = (float*)(smem + SM_D2);

    // ---- stage A tile (128 rows x 128 bf16 = 2 K-halves, SW128): 1 job/thread
    {
        int row = tid >> 1, hf = tid & 1;
        const uint4* src = (const uint4*)(d_Xh + (size_t)(row0 + row) * Dd + hf * 64);
        char* dst = smem + SM_A + hf * 16384;
        #pragma unroll
        for (int i = 0; i < 8; ++i)
            *(uint4*)(dst + sw128(row * 128 + i * 16)) = src[i];
    }
    // ---- stage B chunk 0 via cp.async (1024 x 16B)
    {
        #pragma unroll
        for (int i = 0; i < 4; ++i) {
            int cid = tid + 256 * i;
            int n = cid >> 4, c16 = cid & 15;
            int kh = c16 >> 3, i16 = c16 & 7;
            const char* src = (const char*)(d_Xh + (size_t)n * Dd + kh * 64) + i16 * 16;
            unsigned dst = sb + SM_B + kh * 8192 + sw128(n * 128 + i16 * 16);
            cpasync16(dst, src);
        }
        CP_COMMIT();
    }
    if (tid < 64) csq[tid] = d_sq[tid];
    CP_WAIT0();
    __syncthreads();

    // per-lane ldmatrix geometry
    const int ra   = (lane & 7) + ((lane >> 3) & 1) * 8;
    const int ka16 = (lane >> 4) * 16;
    const int rb   = (lane & 7) + (lane >> 4) * 8;
    const int kb16 = ((lane >> 3) & 1) * 16;
    const int arow = w * 16 + ra;

    // selection state (threads 0..127 own query row m = tid), top-CAND list
    int   cnt = 0, pmax = 0;
    float thresh = CUDART_INF_F;

    for (int c = 0; c < NCHUNK; ++c) {
        float acc[8][4];
        #pragma unroll
        for (int j = 0; j < 8; ++j)
            #pragma unroll
            for (int e = 0; e < 4; ++e) acc[j][e] = 0.f;

        #pragma unroll
        for (int kh = 0; kh < 2; ++kh) {
            const unsigned abase = sb + SM_A + kh * 16384;
            const unsigned bbase = sb + SM_B + kh * 8192;
            #pragma unroll
            for (int ks = 0; ks < 4; ++ks) {
                unsigned a[4];
                ldmx4(a[0], a[1], a[2], a[3],
                      abase + sw128(arow * 128 + ks * 32 + ka16));
                #pragma unroll
                for (int j2 = 0; j2 < 4; ++j2) {
                    unsigned b0, b1, b2, b3;
                    ldmx4(b0, b1, b2, b3,
                          bbase + sw128((16 * j2 + rb) * 128 + ks * 32 + kb16));
                    mma16816(acc[2 * j2],     a, b0, b1);
                    mma16816(acc[2 * j2 + 1], a, b2, b3);
                }
            }
        }

        // d2a = csq - 2*dot -> d2s
        {
            const float* cs = csq + (c & 1) * 64;
            const int m0 = w * 16 + (lane >> 2);
            const int n0 = 2 * (lane & 3);
            #pragma unroll
            for (int j = 0; j < 8; ++j) {
                int n = 8 * j + n0;
                d2s[m0 * 65 + n]           = cs[n]     - 2.0f * acc[j][0];
                d2s[m0 * 65 + n + 1]       = cs[n + 1] - 2.0f * acc[j][1];
                d2s[(m0 + 8) * 65 + n]     = cs[n]     - 2.0f * acc[j][2];
                d2s[(m0 + 8) * 65 + n + 1] = cs[n + 1] - 2.0f * acc[j][3];
            }
        }
        __syncthreads();   // d2s complete; all B reads for chunk c done

        // async-stage B[c+1] (overlaps with selection below)
        if (c + 1 < NCHUNK) {
            const int col0n = (c + 1) * BN;
            #pragma unroll
            for (int i = 0; i < 4; ++i) {
                int cid = tid + 256 * i;
                int n = cid >> 4, c16 = cid & 15;
                int kh = c16 >> 3, i16 = c16 & 7;
                const char* src =
                    (const char*)(d_Xh + (size_t)(col0n + n) * Dd + kh * 64) + i16 * 16;
                unsigned dst = sb + SM_B + kh * 8192 + sw128(n * 128 + i16 * 16);
                cpasync16(dst, src);
            }
            CP_COMMIT();
            if (tid >= 128 && tid < 192)
                csq[((c + 1) & 1) * 64 + (tid - 128)] = d_sq[col0n + tid - 128];
        }

        // approx top-CAND replace-max maintenance (threads 0..127)
        if (tid < BM) {
            const int col0 = c * BN;
            const float* myrow = d2s + tid * 65;
            float* td = topd + tid * 65;
            int*   ti = topi + tid * 65;
            for (int n = 0; n < BN; ++n) {
                float v = myrow[n];
                if (cnt < CAND) {
                    td[cnt] = v; ti[cnt] = col0 + n; ++cnt;
                    if (cnt == CAND) {
                        float mx = -CUDART_INF_F; int pm = 0;
                        #pragma unroll 16
                        for (int q = 0; q < CAND; ++q) {
                            float tq = td[q];
                            if (tq > mx) { mx = tq; pm = q; }
                        }
                        thresh = mx; pmax = pm;
                    }
                } else if (v < thresh) {
                    td[pmax] = v; ti[pmax] = col0 + n;
                    float mx = -CUDART_INF_F; int pm = 0;
                    #pragma unroll 16
                    for (int q = 0; q < CAND; ++q) {
                        float tq = td[q];
                        if (tq > mx) { mx = tq; pm = q; }
                    }
                    thresh = mx; pmax = pm;
                }
            }
        }

        CP_WAIT0();
        __syncthreads();
    }

    if (tid < BM) {
        #pragma unroll 16
        for (int q = 0; q < CAND; ++q)
            d_cand[(size_t)(row0 + tid) * CAND + q] = topi[tid * 65 + q];
    }
}

// ---------------------------------------------------------------------------
// 2b) PASS 2: exact fp32 rescore of 64 candidates -> true top-32
//     rank-count selection (ties broken by candidate slot, deterministic)
// ---------------------------------------------------------------------------
__global__ __launch_bounds__(256, 4) void rescore_kernel(const float* __restrict__ X) {
    __shared__ float q[128];
    __shared__ float vals[CAND];
    __shared__ int   cidx[CAND];
    const int row  = blockIdx.x;
    const int tid  = threadIdx.x;
    const int lane = tid & 31;
    const int w    = tid >> 5;

    if (tid < 128) q[tid] = X[(size_t)row * Dd + tid];
    if (tid < CAND) cidx[tid] = d_cand[(size_t)row * CAND + tid];
    __syncthreads();

    const float4 qv = *(const float4*)(q + lane * 4);
    #pragma unroll
    for (int c = 0; c < CAND / 8; ++c) {
        int j  = w * (CAND / 8) + c;
        int nb = cidx[j];
        float4 v = ((const float4*)(X + (size_t)nb * Dd))[lane];
        float s = v.x * qv.x + v.y * qv.y + v.z * qv.z + v.w * qv.w;
        #pragma unroll
        for (int o = 16; o > 0; o >>= 1) s += __shfl_xor_sync(0xffffffffu, s, o);
        if (lane == 0) vals[j] = d_sq[nb] - 2.0f * s;
    }
    __syncthreads();

    if (tid < CAND) {
        const float v = vals[tid];
        int r = 0;
        #pragma unroll 16
        for (int k = 0; k < CAND; ++k) {
            float vk = vals[k];
            r += (vk < v) || (vk == v && k < tid);
        }
        if (r < Kk) d_idx[(size_t)row * Kk + r] = cidx[tid];
    }
}

// ---------------------------------------------------------------------------
// 3) A = X@W1[:128], B = X@W1[128:]; store u = A - B + b1 and B
// ---------------------------------------------------------------------------
__global__ __launch_bounds__(256, 1) void ab_kernel(const float* __restrict__ X,
                                                    const float* __restrict__ W1,
                                                    const float* __restrict__ b1) {
    extern __shared__ float s[];
    float* w1s = s;            // 256*128
    float* xs  = s + 32768;    // 32*128
    const int tid  = threadIdx.x;
    const int row0 = blockIdx.x * 32;

    for (int t = tid; t < 8192; t += 256)
        ((float4*)w1s)[t] = ((const float4*)W1)[t];
    for (int t = tid; t < 1024; t += 256)
        ((float4*)xs)[t] = ((const float4*)(X + (size_t)row0 * Dd))[t];
    __syncthreads();

    const int h  = tid & 127;
    const int rr = tid >> 7;

    float accA[16], accB[16];
    #pragma unroll
    for (int r = 0; r < 16; ++r) { accA[r] = 0.f; accB[r] = 0.f; }
    const float bb = b1[h];

    #pragma unroll 4
    for (int d = 0; d < 128; ++d) {
        float wa = w1s[d * 128 + h];
        float wb = w1s[(128 + d) * 128 + h];
        #pragma unroll
        for (int r = 0; r < 16; ++r) {
            float x = xs[(rr + 2 * r) * 128 + d];
            accA[r] = fmaf(x, wa, accA[r]);
            accB[r] = fmaf(x, wb, accB[r]);
        }
    }
    #pragma unroll
    for (int r = 0; r < 16; ++r) {
        int i = row0 + rr + 2 * r;
        d_u[(size_t)i * Hh + h] = accA[r] - accB[r] + bb;
        d_B[(size_t)i * Hh + h] = accB[r];
    }
}

// ---------------------------------------------------------------------------
// 4) h_i = relu(u_i + max_{j in knn(i)} B_j)
// ---------------------------------------------------------------------------
__global__ void gmax1_kernel() {
    const int i = blockIdx.x;
    const int h = threadIdx.x;
    const int* ip = d_idx + (size_t)i * Kk;
    float mx = -CUDART_INF_F;
    #pragma unroll 8
    for (int j = 0; j < Kk; ++j) {
        int nb = ip[j];
        mx = fmaxf(mx, d_B[(size_t)nb * Hh + h]);
    }
    float val = d_u[(size_t)i * Hh + h] + mx;
    d_h[(size_t)i * Hh + h] = val > 0.f ? val : 0.f;
}

// ---------------------------------------------------------------------------
// 5) C = h@W2[:128], Dm = h@W2[128:]; store v = C - Dm + b2 and Dm
// ---------------------------------------------------------------------------
__global__ void cd_kernel(const float* __restrict__ W2, const float* __restrict__ b2) {
    __shared__ float w2s[256 * 10];
    __shared__ float hs[32 * 128];
    const int tid  = threadIdx.x;        // 320
    const int row0 = blockIdx.x * 32;

    for (int t = tid; t < 2560; t += 320) w2s[t] = W2[t];
    for (int t = tid; t < 4096; t += 320) hs[t] = d_h[(size_t)row0 * Hh + t];
    __syncthreads();

    const int r = tid / 10;
    const int c = tid % 10;
    float aC = 0.f, aD = 0.f;
    #pragma unroll 8
    for (int hh = 0; hh < 128; ++hh) {
        float x = hs[r * 128 + hh];
        aC = fmaf(x, w2s[hh * 10 + c], aC);
        aD = fmaf(x, w2s[(128 + hh) * 10 + c], aD);
    }
    const int i = row0 + r;
    d_v[(size_t)i * Cc + c]  = aC - aD + b2[c];
    d_Dm[(size_t)i * Cc + c] = aD;
}

// ---------------------------------------------------------------------------
// 6) out_i = v_i + max_{j in knn(i)} Dm_j
// ---------------------------------------------------------------------------
__global__ void out_kernel(float* __restrict__ out) {
    const int tid = threadIdx.x;         // 320
    const int r = tid / 10;
    const int c = tid % 10;
    const int i = blockIdx.x * 32 + r;
    const int* ip = d_idx + (size_t)i * Kk;
    float mx = -CUDART_INF_F;
    #pragma unroll 8
    for (int j = 0; j < Kk; ++j) {
        int nb = ip[j];
        mx = fmaxf(mx, d_Dm[(size_t)nb * Cc + c]);
    }
    out[(size_t)i * Cc + c] = d_v[(size_t)i * Cc + c] + mx;
}

// ---------------------------------------------------------------------------
extern "C" void kernel_launch(void* const* d_in, const int* in_sizes, int n_in,
                              void* d_out, int out_size) {
    const float* X  = (const float*)d_in[0];
    const float* W1 = (const float*)d_in[1];
    const float* b1 = (const float*)d_in[2];
    const float* W2 = (const float*)d_in[3];
    const float* b2 = (const float*)d_in[4];
    float* out = (float*)d_out;

    const int AB_SMEM = (32768 + 4096) * 4;
    cudaFuncSetAttribute(knn_kernel, cudaFuncAttributeMaxDynamicSharedMemorySize, SMEM_TOTAL);
    cudaFuncSetAttribute(ab_kernel,  cudaFuncAttributeMaxDynamicSharedMemorySize, AB_SMEM);

    sq_kernel<<<Np / 8, dim3(32, 8)>>>(X);
    convert_kernel<<<Np * Dd / 256, 256>>>(X);
    knn_kernel<<<Np / BM, 256, SMEM_TOTAL>>>();
    rescore_kernel<<<Np, 256>>>(X);
    ab_kernel<<<Np / 32, 256, AB_SMEM>>>(X, W1, b1);
    gmax1_kernel<<<Np, 128>>>();
    cd_kernel<<<Np / 32, 320>>>(W2, b2);
    out_kernel<<<Np / 32, 320>>>(out);
}

// round 16
// speedup vs baseline: 1.5018x; 1.5018x over previous
#include <cuda_runtime.h>
#include <cuda_bf16.h>
#include <math_constants.h>

#define Np 16384
#define Dd 128
#define Hh 128
#define Cc 10
#define Kk 32
#define CAND 64         // pass-1 candidates per row (top-64 superset of true top-32)

#define BM 128          // query rows per block
#define BN 64           // candidate cols per chunk
#define NCHUNK (Np / BN)

// shared memory byte offsets (pass-1 knn kernel)
#define SM_CSQ  64                           // float[2][64]
#define SM_A    1024                         // 2 half-tiles x 16384 B : 128 rows x 128B SW128
#define SM_B    (SM_A + 2 * 16384)           // 2 half-tiles x 8192 B : 64 rows x 128B SW128
#define SM_D2   (SM_B + 2 * 8192)            // float[128][65]
#define SMEM_TOTAL (SM_D2 + 128 * 65 * 4)    // 83456 B

__device__ __forceinline__ unsigned sw128(unsigned off) { return off ^ ((off >> 3) & 0x70); }

// -------------------- scratch (static device memory) -----------------------
__device__ float d_sq[Np];
__device__ int   d_cand[Np * CAND];
__device__ int   d_idx[Np * Kk];
__device__ float d_u[Np * Hh];
__device__ float d_B[Np * Hh];
__device__ float d_h[Np * Hh];
__device__ float d_v[Np * Cc];
__device__ float d_Dm[Np * Cc];
__device__ __nv_bfloat16 d_Xh[Np * Dd];

// -------------------- ptx helpers ------------------------------------------
__device__ __forceinline__ unsigned smem_u32(const void* p) {
    unsigned a;
    asm("{ .reg .u64 t; cvta.to.shared.u64 t, %1; cvt.u32.u64 %0, t; }" : "=r"(a) : "l"(p));
    return a;
}
__device__ __forceinline__ void ldmx4(unsigned& r0, unsigned& r1, unsigned& r2, unsigned& r3,
                                      unsigned addr) {
    asm volatile("ldmatrix.sync.aligned.m8n8.x4.shared.b16 {%0,%1,%2,%3}, [%4];"
                 : "=r"(r0), "=r"(r1), "=r"(r2), "=r"(r3) : "r"(addr));
}
__device__ __forceinline__ void mma16816(float* d, const unsigned* a, unsigned b0, unsigned b1) {
    asm volatile("mma.sync.aligned.m16n8k16.row.col.f32.bf16.bf16.f32 "
                 "{%0,%1,%2,%3}, {%4,%5,%6,%7}, {%8,%9}, {%0,%1,%2,%3};"
                 : "+f"(d[0]), "+f"(d[1]), "+f"(d[2]), "+f"(d[3])
                 : "r"(a[0]), "r"(a[1]), "r"(a[2]), "r"(a[3]), "r"(b0), "r"(b1));
}
__device__ __forceinline__ void cpasync16(unsigned dst, const void* src) {
    asm volatile("cp.async.cg.shared.global [%0], [%1], 16;" :: "r"(dst), "l"(src) : "memory");
}
#define CP_COMMIT() asm volatile("cp.async.commit_group;" ::: "memory")
#define CP_WAIT0()  asm volatile("cp.async.wait_group 0;" ::: "memory")

// ---------------------------------------------------------------------------
// 0) bf16 copy of X
// ---------------------------------------------------------------------------
__global__ void convert_kernel(const float* __restrict__ X) {
    int i = blockIdx.x * 256 + threadIdx.x;
    d_Xh[i] = __float2bfloat16(X[i]);
}

// ---------------------------------------------------------------------------
// 1) row squared norms
// ---------------------------------------------------------------------------
__global__ void sq_kernel(const float* __restrict__ X) {
    int row = blockIdx.x * 8 + threadIdx.y;
    const float4* xr = (const float4*)(X + (size_t)row * Dd);
    float4 v = xr[threadIdx.x];
    float s = v.x * v.x + v.y * v.y + v.z * v.z + v.w * v.w;
    #pragma unroll
    for (int o = 16; o > 0; o >>= 1) s += __shfl_xor_sync(0xffffffffu, s, o);
    if (threadIdx.x == 0) d_sq[row] = s;
}

// ---------------------------------------------------------------------------
// 2) PASS 1: bf16 mma.sync distance GEMM + warp-parallel approx top-64
//    d2a = sq_j - 2 * dot(h_i, h_j); candidate lists live in registers.
// ---------------------------------------------------------------------------
__global__ __launch_bounds__(256, 1) void knn_kernel() {
    extern __shared__ char smem[];
    const unsigned sb = smem_u32(smem);
    const int tid  = threadIdx.x;
    const int lane = tid & 31;
    const int w    = tid >> 5;
    const int row0 = blockIdx.x * BM;

    float* csq = (float*)(smem + SM_CSQ);
    float* d2s = (float*)(smem + SM_D2);

    // ---- stage A tile (128 rows x 128 bf16 = 2 K-halves, SW128)
    {
        int row = tid >> 1, hf = tid & 1;
        const uint4* src = (const uint4*)(d_Xh + (size_t)(row0 + row) * Dd + hf * 64);
        char* dst = smem + SM_A + hf * 16384;
        #pragma unroll
        for (int i = 0; i < 8; ++i)
            *(uint4*)(dst + sw128(row * 128 + i * 16)) = src[i];
    }
    // ---- stage B chunk 0 via cp.async (1024 x 16B)
    {
        #pragma unroll
        for (int i = 0; i < 4; ++i) {
            int cid = tid + 256 * i;
            int n = cid >> 4, c16 = cid & 15;
            int kh = c16 >> 3, i16 = c16 & 7;
            const char* src = (const char*)(d_Xh + (size_t)n * Dd + kh * 64) + i16 * 16;
            unsigned dst = sb + SM_B + kh * 8192 + sw128(n * 128 + i16 * 16);
            cpasync16(dst, src);
        }
        CP_COMMIT();
    }
    if (tid < 64) csq[tid] = d_sq[tid];
    CP_WAIT0();
    __syncthreads();

    // per-lane ldmatrix geometry
    const int ra   = (lane & 7) + ((lane >> 3) & 1) * 8;
    const int ka16 = (lane >> 4) * 16;
    const int rb   = (lane & 7) + (lane >> 4) * 8;
    const int kb16 = ((lane >> 3) & 1) * 16;
    const int arow = w * 16 + ra;

    // register-resident top-64 lists: warp w owns rows w*16 .. w*16+15.
    // Lane holds 2 (value, col) slots per row; lane r (r<16) caches row r's
    // threshold (list max) and its position (lane<<1 | slot).
    float v0_[16], v1_[16];
    int   i0_[16], i1_[16];
    float thrState = 0.f;
    unsigned mpState = 0;

    for (int c = 0; c < NCHUNK; ++c) {
        float acc[8][4];
        #pragma unroll
        for (int j = 0; j < 8; ++j)
            #pragma unroll
            for (int e = 0; e < 4; ++e) acc[j][e] = 0.f;

        #pragma unroll
        for (int kh = 0; kh < 2; ++kh) {
            const unsigned abase = sb + SM_A + kh * 16384;
            const unsigned bbase = sb + SM_B + kh * 8192;
            #pragma unroll
            for (int ks = 0; ks < 4; ++ks) {
                unsigned a[4];
                ldmx4(a[0], a[1], a[2], a[3],
                      abase + sw128(arow * 128 + ks * 32 + ka16));
                #pragma unroll
                for (int j2 = 0; j2 < 4; ++j2) {
                    unsigned b0, b1, b2, b3;
                    ldmx4(b0, b1, b2, b3,
                          bbase + sw128((16 * j2 + rb) * 128 + ks * 32 + kb16));
                    mma16816(acc[2 * j2],     a, b0, b1);
                    mma16816(acc[2 * j2 + 1], a, b2, b3);
                }
            }
        }

        // d2a = csq - 2*dot -> d2s (warp writes only its own 16 rows)
        {
            const float* cs = csq + (c & 1) * 64;
            const int m0 = w * 16 + (lane >> 2);
            const int n0 = 2 * (lane & 3);
            #pragma unroll
            for (int j = 0; j < 8; ++j) {
                int n = 8 * j + n0;
                d2s[m0 * 65 + n]           = cs[n]     - 2.0f * acc[j][0];
                d2s[m0 * 65 + n + 1]       = cs[n + 1] - 2.0f * acc[j][1];
                d2s[(m0 + 8) * 65 + n]     = cs[n]     - 2.0f * acc[j][2];
                d2s[(m0 + 8) * 65 + n + 1] = cs[n + 1] - 2.0f * acc[j][3];
            }
        }
        __syncthreads();   // all Bs reads (MMA) done before restaging

        // async-stage B[c+1] (overlaps with selection below)
        if (c + 1 < NCHUNK) {
            const int col0n = (c + 1) * BN;
            #pragma unroll
            for (int i = 0; i < 4; ++i) {
                int cid = tid + 256 * i;
                int n = cid >> 4, c16 = cid & 15;
                int kh = c16 >> 3, i16 = c16 & 7;
                const char* src =
                    (const char*)(d_Xh + (size_t)(col0n + n) * Dd + kh * 64) + i16 * 16;
                unsigned dst = sb + SM_B + kh * 8192 + sw128(n * 128 + i16 * 16);
                cpasync16(dst, src);
            }
            CP_COMMIT();
            if (tid >= 128 && tid < 192)
                csq[((c + 1) & 1) * 64 + (tid - 128)] = d_sq[col0n + tid - 128];
        }

        // warp-parallel top-64 maintenance on own rows (register lists)
        {
            const int col0 = c * BN;
            #pragma unroll
            for (int r = 0; r < 16; ++r) {
                const int row = w * 16 + r;
                float nv0 = d2s[row * 65 + lane];
                float nv1 = d2s[row * 65 + 32 + lane];
                if (c == 0) {
                    v0_[r] = nv0; i0_[r] = lane;
                    v1_[r] = nv1; i1_[r] = 32 + lane;
                    float m = fmaxf(nv0, nv1);
                    unsigned p = ((unsigned)lane << 1) | (nv1 > nv0 ? 1u : 0u);
                    #pragma unroll
                    for (int o = 16; o; o >>= 1) {
                        float mo = __shfl_xor_sync(0xffffffffu, m, o);
                        unsigned po = __shfl_xor_sync(0xffffffffu, p, o);
                        if (mo > m) { m = mo; p = po; }
                    }
                    if (lane == r) { thrState = m; mpState = p; }
                } else {
                    float tv = __shfl_sync(0xffffffffu, thrState, r);
                    unsigned mp = __shfl_sync(0xffffffffu, mpState, r);
                    unsigned q0 = __ballot_sync(0xffffffffu, nv0 < tv);
                    unsigned q1 = __ballot_sync(0xffffffffu, nv1 < tv);
                    while (q0 | q1) {
                        bool use0 = (q0 != 0);
                        unsigned mm = use0 ? q0 : q1;
                        int sl = __ffs(mm) - 1;
                        float c0 = __shfl_sync(0xffffffffu, nv0, sl);
                        float c1 = __shfl_sync(0xffffffffu, nv1, sl);
                        float cv = use0 ? c0 : c1;
                        int col = col0 + sl + (use0 ? 0 : 32);
                        if (use0) q0 &= q0 - 1; else q1 &= q1 - 1;
                        if (cv < tv) {       // recheck vs evolving threshold
                            if (lane == (int)(mp >> 1)) {
                                if (mp & 1) { v1_[r] = cv; i1_[r] = col; }
                                else        { v0_[r] = cv; i0_[r] = col; }
                            }
                            float m = fmaxf(v0_[r], v1_[r]);
                            unsigned p = ((unsigned)lane << 1) | (v1_[r] > v0_[r] ? 1u : 0u);
                            #pragma unroll
                            for (int o = 16; o; o >>= 1) {
                                float mo = __shfl_xor_sync(0xffffffffu, m, o);
                                unsigned po = __shfl_xor_sync(0xffffffffu, p, o);
                                if (mo > m) { m = mo; p = po; }
                            }
                            tv = m; mp = p;
                        }
                    }
                    if (lane == r) { thrState = tv; mpState = mp; }
                }
            }
        }

        CP_WAIT0();
        __syncthreads();
    }

    // write candidate lists
    #pragma unroll
    for (int r = 0; r < 16; ++r) {
        int grow = row0 + w * 16 + r;
        d_cand[(size_t)grow * CAND + lane]      = i0_[r];
        d_cand[(size_t)grow * CAND + 32 + lane] = i1_[r];
    }
}

// ---------------------------------------------------------------------------
// 2b) PASS 2: exact fp32 rescore of 64 candidates -> true top-32
// ---------------------------------------------------------------------------
__global__ __launch_bounds__(256, 4) void rescore_kernel(const float* __restrict__ X) {
    __shared__ float q[128];
    __shared__ float vals[CAND];
    __shared__ int   cidx[CAND];
    const int row  = blockIdx.x;
    const int tid  = threadIdx.x;
    const int lane = tid & 31;
    const int w    = tid >> 5;

    if (tid < 128) q[tid] = X[(size_t)row * Dd + tid];
    if (tid < CAND) cidx[tid] = d_cand[(size_t)row * CAND + tid];
    __syncthreads();

    const float4 qv = *(const float4*)(q + lane * 4);
    #pragma unroll
    for (int c = 0; c < CAND / 8; ++c) {
        int j  = w * (CAND / 8) + c;
        int nb = cidx[j];
        float4 v = ((const float4*)(X + (size_t)nb * Dd))[lane];
        float s = v.x * qv.x + v.y * qv.y + v.z * qv.z + v.w * qv.w;
        #pragma unroll
        for (int o = 16; o > 0; o >>= 1) s += __shfl_xor_sync(0xffffffffu, s, o);
        if (lane == 0) vals[j] = d_sq[nb] - 2.0f * s;
    }
    __syncthreads();

    if (tid < CAND) {
        const float v = vals[tid];
        int r = 0;
        #pragma unroll 16
        for (int k = 0; k < CAND; ++k) {
            float vk = vals[k];
            r += (vk < v) || (vk == v && k < tid);
        }
        if (r < Kk) d_idx[(size_t)row * Kk + r] = cidx[tid];
    }
}

// ---------------------------------------------------------------------------
// 3) A = X@W1[:128], B = X@W1[128:]; store u = A - B + b1 and B
// ---------------------------------------------------------------------------
__global__ __launch_bounds__(256, 1) void ab_kernel(const float* __restrict__ X,
                                                    const float* __restrict__ W1,
                                                    const float* __restrict__ b1) {
    extern __shared__ float s[];
    float* w1s = s;            // 256*128
    float* xs  = s + 32768;    // 32*128
    const int tid  = threadIdx.x;
    const int row0 = blockIdx.x * 32;

    for (int t = tid; t < 8192; t += 256)
        ((float4*)w1s)[t] = ((const float4*)W1)[t];
    for (int t = tid; t < 1024; t += 256)
        ((float4*)xs)[t] = ((const float4*)(X + (size_t)row0 * Dd))[t];
    __syncthreads();

    const int h  = tid & 127;
    const int rr = tid >> 7;

    float accA[16], accB[16];
    #pragma unroll
    for (int r = 0; r < 16; ++r) { accA[r] = 0.f; accB[r] = 0.f; }
    const float bb = b1[h];

    #pragma unroll 4
    for (int d = 0; d < 128; ++d) {
        float wa = w1s[d * 128 + h];
        float wb = w1s[(128 + d) * 128 + h];
        #pragma unroll
        for (int r = 0; r < 16; ++r) {
            float x = xs[(rr + 2 * r) * 128 + d];
            accA[r] = fmaf(x, wa, accA[r]);
            accB[r] = fmaf(x, wb, accB[r]);
        }
    }
    #pragma unroll
    for (int r = 0; r < 16; ++r) {
        int i = row0 + rr + 2 * r;
        d_u[(size_t)i * Hh + h] = accA[r] - accB[r] + bb;
        d_B[(size_t)i * Hh + h] = accB[r];
    }
}

// ---------------------------------------------------------------------------
// 4) h_i = relu(u_i + max_{j in knn(i)} B_j)
// ---------------------------------------------------------------------------
__global__ void gmax1_kernel() {
    const int i = blockIdx.x;
    const int h = threadIdx.x;
    const int* ip = d_idx + (size_t)i * Kk;
    float mx = -CUDART_INF_F;
    #pragma unroll 8
    for (int j = 0; j < Kk; ++j) {
        int nb = ip[j];
        mx = fmaxf(mx, d_B[(size_t)nb * Hh + h]);
    }
    float val = d_u[(size_t)i * Hh + h] + mx;
    d_h[(size_t)i * Hh + h] = val > 0.f ? val : 0.f;
}

// ---------------------------------------------------------------------------
// 5) C = h@W2[:128], Dm = h@W2[128:]; store v = C - Dm + b2 and Dm
// ---------------------------------------------------------------------------
__global__ void cd_kernel(const float* __restrict__ W2, const float* __restrict__ b2) {
    __shared__ float w2s[256 * 10];
    __shared__ float hs[32 * 128];
    const int tid  = threadIdx.x;        // 320
    const int row0 = blockIdx.x * 32;

    for (int t = tid; t < 2560; t += 320) w2s[t] = W2[t];
    for (int t = tid; t < 4096; t += 320) hs[t] = d_h[(size_t)row0 * Hh + t];
    __syncthreads();

    const int r = tid / 10;
    const int c = tid % 10;
    float aC = 0.f, aD = 0.f;
    #pragma unroll 8
    for (int hh = 0; hh < 128; ++hh) {
        float x = hs[r * 128 + hh];
        aC = fmaf(x, w2s[hh * 10 + c], aC);
        aD = fmaf(x, w2s[(128 + hh) * 10 + c], aD);
    }
    const int i = row0 + r;
    d_v[(size_t)i * Cc + c]  = aC - aD + b2[c];
    d_Dm[(size_t)i * Cc + c] = aD;
}

// ---------------------------------------------------------------------------
// 6) out_i = v_i + max_{j in knn(i)} Dm_j
// ---------------------------------------------------------------------------
__global__ void out_kernel(float* __restrict__ out) {
    const int tid = threadIdx.x;         // 320
    const int r = tid / 10;
    const int c = tid % 10;
    const int i = blockIdx.x * 32 + r;
    const int* ip = d_idx + (size_t)i * Kk;
    float mx = -CUDART_INF_F;
    #pragma unroll 8
    for (int j = 0; j < Kk; ++j) {
        int nb = ip[j];
        mx = fmaxf(mx, d_Dm[(size_t)nb * Cc + c]);
    }
    out[(size_t)i * Cc + c] = d_v[(size_t)i * Cc + c] + mx;
}

// ---------------------------------------------------------------------------
extern "C" void kernel_launch(void* const* d_in, const int* in_sizes, int n_in,
                              void* d_out, int out_size) {
    const float* X  = (const float*)d_in[0];
    const float* W1 = (const float*)d_in[1];
    const float* b1 = (const float*)d_in[2];
    const float* W2 = (const float*)d_in[3];
    const float* b2 = (const float*)d_in[4];
    float* out = (float*)d_out;

    const int AB_SMEM = (32768 + 4096) * 4;
    cudaFuncSetAttribute(knn_kernel, cudaFuncAttributeMaxDynamicSharedMemorySize, SMEM_TOTAL);
    cudaFuncSetAttribute(ab_kernel,  cudaFuncAttributeMaxDynamicSharedMemorySize, AB_SMEM);

    sq_kernel<<<Np / 8, dim3(32, 8)>>>(X);
    convert_kernel<<<Np * Dd / 256, 256>>>(X);
    knn_kernel<<<Np / BM, 256, SMEM_TOTAL>>>();
    rescore_kernel<<<Np, 256>>>(X);
    ab_kernel<<<Np / 32, 256, AB_SMEM>>>(X, W1, b1);
    gmax1_kernel<<<Np, 128>>>();
    cd_kernel<<<Np / 32, 320>>>(W2, b2);
    out_kernel<<<Np / 32, 320>>>(out);
}